// round 9
// baseline (speedup 1.0000x reference)
#include <cuda_runtime.h>
#include <math.h>
#include <cstdint>

#define N_TOK   8192
#define DM      256
#define NE      16
#define NVIEW   3
#define TOPK    4
#define HID     1024
#define TM      64

// ---- ffn smem layout (float indices) ----
#define XP_F    0           // Xperm A-frag order: [4mt][32ks][32lane][4] = 16384
#define HP_F    16384       // Hperm double buffer: 2 x [4mt][16ks][32lane][4] = 16384
#define B1_F    32768       // 1024
#define B2_F    33792       // 256
#define TOK_F   34048       // 64 ints
#define GATE_F  34112       // 64
#define SMEM_FLOATS 34176
#define SMEM_BYTES  (SMEM_FLOATS * 4)    // 136704 -> 1 block x 512 thr / SM

// ---------------- device scratch ----------------
__device__ int   g_cnt [NVIEW * NE];
__device__ int   g_tok [NVIEW * NE * N_TOK];
__device__ float g_gate[NVIEW * NE * N_TOK];
__device__ float g_w1p [NE * DM * HID];   // W1, tf32-rounded, B-frag order
__device__ float g_w2p [NE * HID * DM];   // W2, tf32-rounded, B-frag order

// ---------------- helpers ----------------
__device__ __forceinline__ float tf32r(float x) {
    asm("cvt.rna.tf32.f32 %0, %1;" : "=f"(x) : "f"(x));
    return x;
}
__device__ __forceinline__ float4 tf32r4(float4 v) {
    v.x = tf32r(v.x); v.y = tf32r(v.y); v.z = tf32r(v.z); v.w = tf32r(v.w);
    return v;
}
__device__ __forceinline__ float d4(float4 a, float4 b) {
    return a.x * b.x + a.y * b.y + a.z * b.z + a.w * b.w;
}
__device__ __forceinline__ float wredsum(float x) {
#pragma unroll
    for (int o = 16; o > 0; o >>= 1) x += __shfl_xor_sync(0xffffffffu, x, o);
    return x;
}
__device__ __forceinline__ float gelu_exact(float x) {
    return 0.5f * x * (1.0f + erff(x * 0.70710678118654752440f));
}
// m16n8k8 tf32 mma: D += A*B
__device__ __forceinline__ void mma8(float4& d, const uint4& a,
                                     uint32_t b0, uint32_t b1) {
    asm volatile(
        "mma.sync.aligned.m16n8k8.row.col.f32.tf32.tf32.f32 "
        "{%0,%1,%2,%3}, {%4,%5,%6,%7}, {%8,%9}, {%0,%1,%2,%3};"
        : "+f"(d.x), "+f"(d.y), "+f"(d.z), "+f"(d.w)
        : "r"(a.x), "r"(a.y), "r"(a.z), "r"(a.w), "r"(b0), "r"(b1));
}
__device__ __forceinline__ void red2(float* p, float a, float b) {
    asm volatile("red.global.add.v2.f32 [%0], {%1, %2};"
                 :: "l"(p), "f"(a), "f"(b) : "memory");
}

// ---------------- kernel 0: prep (round+permute weights, zero cnt & out) ----
__global__ void prep_kernel(const float* __restrict__ W1,
                            const float* __restrict__ W2,
                            float* __restrict__ out) {
    __shared__ float s[256 * 36];
    int tid = threadIdx.x, b = blockIdx.x;
    if (b == 0 && tid < NVIEW * NE) g_cnt[tid] = 0;
    {   // zero out: 524288 float4 over 1024 blocks
        float4* o4 = (float4*)out;
        int zb = b * 512 + tid;
        o4[zb]       = make_float4(0.f, 0.f, 0.f, 0.f);
        o4[zb + 256] = make_float4(0.f, 0.f, 0.f, 0.f);
    }
    if (b < 512) {
        int e = b >> 5, jc = b & 31;
        for (int i = tid; i < 2048; i += 256) {
            int d = i >> 3, j4 = i & 7;
            float4 v = ((const float4*)(W1 + ((size_t)e * DM + d) * HID + jc * 32))[j4];
            *(float4*)&s[d * 36 + j4 * 4] = tf32r4(v);
        }
        __syncthreads();
        float4* dst = (float4*)g_w1p + (size_t)(e * 32 + jc) * 2048;
        for (int o = tid; o < 2048; o += 256) {
            int nt = o >> 9, kp = (o >> 5) & 15, ln = o & 31;
            int tig = ln & 3, g = ln >> 2;
            int jl = nt * 8 + g;
            float4 v;
            v.x = s[(16 * kp + tig) * 36 + jl];
            v.y = s[(16 * kp + tig + 4) * 36 + jl];
            v.z = s[(16 * kp + 8 + tig) * 36 + jl];
            v.w = s[(16 * kp + 8 + tig + 4) * 36 + jl];
            dst[o] = v;
        }
    } else {
        int e = (b - 512) >> 5, jc = (b - 512) & 31;
        for (int i = tid; i < 2048; i += 256) {
            int rl = i >> 6, n4 = i & 63;
            float4 v = ((const float4*)(W2 + ((size_t)e * HID + jc * 32 + rl) * DM))[n4];
            *(float4*)&s[rl * 260 + n4 * 4] = tf32r4(v);
        }
        __syncthreads();
        float4* dst = (float4*)g_w2p + (size_t)(e * 32 + jc) * 2048;
        for (int o = tid; o < 2048; o += 256) {
            int nt = o >> 6, kp = (o >> 5) & 1, ln = o & 31;
            int tig = ln & 3, g = ln >> 2;
            int n = nt * 8 + g;
            float4 v;
            v.x = s[(16 * kp + tig) * 260 + n];
            v.y = s[(16 * kp + tig + 4) * 260 + n];
            v.z = s[(16 * kp + 8 + tig) * 260 + n];
            v.w = s[(16 * kp + 8 + tig + 4) * 260 + n];
            dst[o] = v;
        }
    }
}

// ---------------- kernel 1: router (bit-exact fp32 sequence, unchanged) ------
__global__ void router_kernel(const float* __restrict__ v0,
                              const float* __restrict__ v1,
                              const float* __restrict__ v2,
                              const float* __restrict__ rw,
                              const float* __restrict__ keys) {
    int vi   = blockIdx.y;
    int warp = threadIdx.x >> 5;
    int lane = threadIdx.x & 31;
    int tok  = blockIdx.x * 8 + warp;
    if (tok >= N_TOK) return;

    const float* vbase = (vi == 0) ? v0 : ((vi == 1) ? v1 : v2);
    const float* v = vbase + tok * DM;

    float4 a = ((const float4*)v)[lane];
    float4 b = ((const float4*)v)[lane + 32];

    float vv = wredsum(d4(a, a) + d4(b, b));

    const float* rwv = rw + (size_t)vi * NE * DM;
    float lg[NE];
#pragma unroll
    for (int e = 0; e < NE; e++) {
        const float4* kp = (const float4*)(keys + e * DM);
        const float4* rp = (const float4*)(rwv + e * DM);
        float4 k1 = kp[lane], k2 = kp[lane + 32];
        float4 r1 = rp[lane], r2 = rp[lane + 32];
        float dk = wredsum(d4(a, k1) + d4(b, k2));
        float dr = wredsum(d4(a, r1) + d4(b, r2));
        float kk = wredsum(d4(k1, k1) + d4(k2, k2));
        float sq = (vv + kk) - 2.0f * dk;
        lg[e] = (-sq) + dr;
    }

    if (lane == 0) {
        unsigned chosen = 0;
        float tv[TOPK];
        int   ti[TOPK];
#pragma unroll
        for (int k = 0; k < TOPK; k++) {
            float m = -1e30f; int mi = 0;
#pragma unroll
            for (int e = 0; e < NE; e++) {
                if (!((chosen >> e) & 1u) && lg[e] > m) { m = lg[e]; mi = e; }
            }
            tv[k] = m; ti[k] = mi; chosen |= (1u << mi);
        }
        float s = 0.f;
        float ex[TOPK];
#pragma unroll
        for (int k = 0; k < TOPK; k++) { ex[k] = expf(tv[k] - tv[0]); s += ex[k]; }
        float inv = 1.0f / s;
#pragma unroll
        for (int k = 0; k < TOPK; k++) {
            int ge  = vi * NE + ti[k];
            int pos = atomicAdd(&g_cnt[ge], 1);
            g_tok [ge * N_TOK + pos] = tok;
            g_gate[ge * N_TOK + pos] = ex[k] * inv;
        }
    }
}

// ------- kernel 2: grouped FFN, producer/consumer warp specialization -------
extern "C" __global__ void __launch_bounds__(512, 1)
ffn_kernel(const float* __restrict__ v0, const float* __restrict__ v1,
           const float* __restrict__ v2,
           const float* __restrict__ b1, const float* __restrict__ b2,
           float* __restrict__ out) {
    extern __shared__ float sm[];
    int tid = threadIdx.x, wid = tid >> 5, lane = tid & 31;
    int vi = blockIdx.z, e = blockIdx.y, g0 = vi * NE + e;
    int cnt = g_cnt[g0];
    int t0 = blockIdx.x * TM;
    if (t0 >= cnt) return;
    int rows = min(TM, cnt - t0);

    int*   s_tok  = (int*)&sm[TOK_F];
    float* s_gate = &sm[GATE_F];
    if (tid < TM) {
        int idx = t0 + tid;
        s_tok [tid] = (idx < cnt) ? g_tok [g0 * N_TOK + idx] : 0;
        s_gate[tid] = (idx < cnt) ? g_gate[g0 * N_TOK + idx] : 0.0f;
    }
    for (int i = tid; i < HID; i += 512) sm[B1_F + i] = b1[(size_t)e * HID + i];
    if (tid < DM) sm[B2_F + tid] = b2[(size_t)e * DM + tid];
    __syncthreads();

    const float* V = (vi == 0) ? v0 : ((vi == 1) ? v1 : v2);

    // ---- gather X -> A-fragment-permuted smem (tf32-rna) ----
    for (int i = tid; i < TM * 64; i += 512) {
        int r = i >> 6, c4 = i & 63;
        float4 v = make_float4(0.f, 0.f, 0.f, 0.f);
        if (r < rows) v = tf32r4(((const float4*)(V + (size_t)s_tok[r] * DM))[c4]);
        int mt = r >> 4, pair = (r >> 3) & 1, gg2 = r & 7;
        int ks = c4 >> 1, q = pair + 2 * (c4 & 1);
        int base = ((mt * 32 + ks) * 32 + gg2 * 4) * 4 + q;
        sm[XP_F + base     ] = v.x;
        sm[XP_F + base + 4 ] = v.y;
        sm[XP_F + base + 8 ] = v.z;
        sm[XP_F + base + 12] = v.w;
    }
    __syncthreads();

    const uint4* XP  = (const uint4*)&sm[XP_F];
    const uint4* W1P = (const uint4*)g_w1p + (size_t)(e * 32) * 2048;
    const uint4* W2P = (const uint4*)g_w2p + (size_t)(e * 32) * 2048;
    const int gg = lane >> 2, cc = lane & 3;
    const bool producer = wid < 8;
    const int m1 = wid & 1, nc = wid >> 1;   // producer roles (m-half, chunk)
    const int o2 = wid - 8;                  // consumer role (n-octet)

    float4 acc[4][4];   // consumers only: warp tile m64 x n32
#pragma unroll
    for (int i = 0; i < 4; i++)
#pragma unroll
        for (int j = 0; j < 4; j++) acc[i][j] = make_float4(0.f, 0.f, 0.f, 0.f);

#pragma unroll 1
    for (int sc = 0; sc < 9; sc++) {
        if (producer && sc < 8) {
            // ========= GEMM1: chunk jc = sc*4+nc, warp tile m32 x n32 =========
            int jc = sc * 4 + nc;
            float4 a1[2][4];
#pragma unroll
            for (int i = 0; i < 2; i++)
#pragma unroll
                for (int j = 0; j < 4; j++) a1[i][j] = make_float4(0.f, 0.f, 0.f, 0.f);
            const uint4* W1j = W1P + (size_t)jc * 2048 + lane;
            uint4 bb[4][4];            // depth-4 prefetch over k16 steps
#pragma unroll
            for (int p = 0; p < 4; p++)
#pragma unroll
                for (int nt = 0; nt < 4; nt++)
                    bb[p][nt] = W1j[nt * 512 + p * 32];
#pragma unroll
            for (int kp = 0; kp < 16; kp++) {
                uint4 alo0 = XP[((2 * m1) * 32 + 2 * kp) * 32 + lane];
                uint4 ahi0 = XP[((2 * m1) * 32 + 2 * kp + 1) * 32 + lane];
                uint4 alo1 = XP[((2 * m1 + 1) * 32 + 2 * kp) * 32 + lane];
                uint4 ahi1 = XP[((2 * m1 + 1) * 32 + 2 * kp + 1) * 32 + lane];
#pragma unroll
                for (int nt = 0; nt < 4; nt++) {
                    uint4 bc = bb[kp & 3][nt];
                    mma8(a1[0][nt], alo0, bc.x, bc.y);
                    mma8(a1[0][nt], ahi0, bc.z, bc.w);
                    mma8(a1[1][nt], alo1, bc.x, bc.y);
                    mma8(a1[1][nt], ahi1, bc.z, bc.w);
                }
                if (kp + 4 < 16) {
#pragma unroll
                    for (int nt = 0; nt < 4; nt++)
                        bb[kp & 3][nt] = W1j[nt * 512 + (kp + 4) * 32];
                }
            }
            // ---- bias + exact GELU -> H[sc&1] (A-frag order, tf32-rna) ----
            float* HB = &sm[HP_F + (sc & 1) * 8192];
#pragma unroll
            for (int mt2 = 0; mt2 < 2; mt2++) {
                int mt = 2 * m1 + mt2;
#pragma unroll
                for (int nt = 0; nt < 4; nt++) {
                    int ks = nc * 4 + nt;          // k8 index within superchunk
                    int c0 = jc * 32 + nt * 8 + 2 * cc;
                    float bx = sm[B1_F + c0];
                    float by = sm[B1_F + c0 + 1];
                    float4 v = a1[mt2][nt];
                    int base = ((mt * 16 + ks) * 32 + gg * 4) * 4
                             + 2 * (cc >> 1) + 8 * (cc & 1);
                    HB[base    ] = tf32r(gelu_exact(v.x + bx));
                    HB[base + 4] = tf32r(gelu_exact(v.y + by));
                    HB[base + 1] = tf32r(gelu_exact(v.z + bx));
                    HB[base + 5] = tf32r(gelu_exact(v.w + by));
                }
            }
        }
        if (!producer && sc > 0) {
            // ========= GEMM2: stage sc-1, warp tile m64 x n32, K = 128 =======
            int scp = sc - 1;
            const uint4* HPl = (const uint4*)&sm[HP_F + (scp & 1) * 8192];
            const int nb = o2 * 4;
            uint4 wb[2][4];
#pragma unroll
            for (int nt = 0; nt < 4; nt++) {
                wb[0][nt] = W2P[(size_t)(scp * 4) * 2048 + (nb + nt) * 64 + lane];
                wb[1][nt] = W2P[(size_t)(scp * 4) * 2048 + (nb + nt) * 64 + 32 + lane];
            }
#pragma unroll
            for (int kq = 0; kq < 8; kq++) {
                uint4 bc[4];
#pragma unroll
                for (int nt = 0; nt < 4; nt++) bc[nt] = wb[kq & 1][nt];
                if (kq + 2 < 8) {
                    size_t jb = (size_t)(scp * 4 + ((kq + 2) >> 1)) * 2048
                              + ((kq + 2) & 1) * 32;
#pragma unroll
                    for (int nt = 0; nt < 4; nt++)
                        wb[kq & 1][nt] = W2P[jb + (nb + nt) * 64 + lane];
                }
#pragma unroll
                for (int mt = 0; mt < 4; mt++) {
                    uint4 hlo = HPl[(mt * 16 + 2 * kq) * 32 + lane];
                    uint4 hhi = HPl[(mt * 16 + 2 * kq + 1) * 32 + lane];
#pragma unroll
                    for (int nt = 0; nt < 4; nt++) {
                        mma8(acc[mt][nt], hlo, bc[nt].x, bc[nt].y);
                        mma8(acc[mt][nt], hhi, bc[nt].z, bc[nt].w);
                    }
                }
            }
        }
        __syncthreads();   // stage boundary: H[sc&1] published, H[(sc-1)&1] consumed
    }

    // ---- epilogue (consumers): out[tok,:] += gate * (acc + b2) ----
    if (!producer) {
#pragma unroll
        for (int nt = 0; nt < 4; nt++) {
            int col = (o2 * 4 + nt) * 8 + 2 * cc;
            float b2a = sm[B2_F + col], b2b = sm[B2_F + col + 1];
#pragma unroll
            for (int mt = 0; mt < 4; mt++) {
                float4 f = acc[mt][nt];
                int ra = mt * 16 + gg;
                int rb = ra + 8;
                if (ra < rows) {
                    float gt = s_gate[ra];
                    red2(out + (size_t)s_tok[ra] * DM + col,
                         gt * (f.x + b2a), gt * (f.y + b2b));
                }
                if (rb < rows) {
                    float gt = s_gate[rb];
                    red2(out + (size_t)s_tok[rb] * DM + col,
                         gt * (f.z + b2a), gt * (f.w + b2b));
                }
            }
        }
    }
}

// ---------------- launch ----------------
extern "C" void kernel_launch(void* const* d_in, const int* in_sizes, int n_in,
                              void* d_out, int out_size) {
    const float* v0   = (const float*)d_in[0];
    const float* v1   = (const float*)d_in[1];
    const float* v2   = (const float*)d_in[2];
    const float* rw   = (const float*)d_in[3];
    const float* keys = (const float*)d_in[4];
    const float* W1   = (const float*)d_in[5];
    const float* b1   = (const float*)d_in[6];
    const float* W2   = (const float*)d_in[7];
    const float* b2   = (const float*)d_in[8];
    float* out = (float*)d_out;

    cudaFuncSetAttribute(ffn_kernel, cudaFuncAttributeMaxDynamicSharedMemorySize,
                         SMEM_BYTES);

    prep_kernel<<<1024, 256, 0, 0>>>(W1, W2, out);

    dim3 rgrid(N_TOK / 8, NVIEW, 1);
    router_kernel<<<rgrid, 256, 0, 0>>>(v0, v1, v2, rw, keys);

    dim3 fgrid(N_TOK / TM, NE, NVIEW);   // 128 x 16 x 3, most blocks exit early
    ffn_kernel<<<fgrid, 512, SMEM_BYTES, 0>>>(v0, v1, v2, b1, b2, out);
}

// round 10
// speedup vs baseline: 1.3993x; 1.3993x over previous
#include <cuda_runtime.h>
#include <math.h>
#include <cstdint>

#define N_TOK   8192
#define DM      256
#define NE      16
#define NVIEW   3
#define TOPK    4
#define HID     1024
#define TM      64

// ---- ffn smem layout (float indices) ----
#define XP_F    0           // Xperm A-frag order: [4mt][32ks][32lane][4] = 16384
#define HP_F    16384       // Hperm double buffer: 2 x [4mt][8ks][32lane][4] = 8192
#define B1_F    24576       // 1024
#define B2_F    25600       // 256
#define TOK_F   25856       // 64 ints
#define GATE_F  25920       // 64
#define SMEM_FLOATS 25984
#define SMEM_BYTES  (SMEM_FLOATS * 4)    // 103936 -> 2 blocks/SM

// ---------------- device scratch ----------------
__device__ int   g_cnt [NVIEW * NE];
__device__ int   g_tok [NVIEW * NE * N_TOK];
__device__ float g_gate[NVIEW * NE * N_TOK];
__device__ float g_w1p [NE * DM * HID];   // W1, tf32-rounded, B-frag order
__device__ float g_w2p [NE * HID * DM];   // W2, tf32-rounded, B-frag order

// ---------------- helpers ----------------
__device__ __forceinline__ float tf32r(float x) {
    asm("cvt.rna.tf32.f32 %0, %1;" : "=f"(x) : "f"(x));
    return x;
}
__device__ __forceinline__ float4 tf32r4(float4 v) {
    v.x = tf32r(v.x); v.y = tf32r(v.y); v.z = tf32r(v.z); v.w = tf32r(v.w);
    return v;
}
__device__ __forceinline__ float d4(float4 a, float4 b) {
    return a.x * b.x + a.y * b.y + a.z * b.z + a.w * b.w;
}
__device__ __forceinline__ float wredsum(float x) {
#pragma unroll
    for (int o = 16; o > 0; o >>= 1) x += __shfl_xor_sync(0xffffffffu, x, o);
    return x;
}
__device__ __forceinline__ float gelu_exact(float x) {
    return 0.5f * x * (1.0f + erff(x * 0.70710678118654752440f));
}
// m16n8k8 tf32 mma: D += A*B
__device__ __forceinline__ void mma8(float4& d, const uint4& a,
                                     uint32_t b0, uint32_t b1) {
    asm volatile(
        "mma.sync.aligned.m16n8k8.row.col.f32.tf32.tf32.f32 "
        "{%0,%1,%2,%3}, {%4,%5,%6,%7}, {%8,%9}, {%0,%1,%2,%3};"
        : "+f"(d.x), "+f"(d.y), "+f"(d.z), "+f"(d.w)
        : "r"(a.x), "r"(a.y), "r"(a.z), "r"(a.w), "r"(b0), "r"(b1));
}
__device__ __forceinline__ void red2(float* p, float a, float b) {
    asm volatile("red.global.add.v2.f32 [%0], {%1, %2};"
                 :: "l"(p), "f"(a), "f"(b) : "memory");
}

// ---------------- kernel 0: prep (round+permute weights, zero cnt & out) ----
__global__ void prep_kernel(const float* __restrict__ W1,
                            const float* __restrict__ W2,
                            float* __restrict__ out) {
    __shared__ float s[256 * 36];
    int tid = threadIdx.x, b = blockIdx.x;
    if (b == 0 && tid < NVIEW * NE) g_cnt[tid] = 0;
    {   // zero out: 524288 float4 over 1024 blocks
        float4* o4 = (float4*)out;
        int zb = b * 512 + tid;
        o4[zb]       = make_float4(0.f, 0.f, 0.f, 0.f);
        o4[zb + 256] = make_float4(0.f, 0.f, 0.f, 0.f);
    }
    if (b < 512) {
        int e = b >> 5, jc = b & 31;
        for (int i = tid; i < 2048; i += 256) {
            int d = i >> 3, j4 = i & 7;
            float4 v = ((const float4*)(W1 + ((size_t)e * DM + d) * HID + jc * 32))[j4];
            *(float4*)&s[d * 36 + j4 * 4] = tf32r4(v);
        }
        __syncthreads();
        float4* dst = (float4*)g_w1p + (size_t)(e * 32 + jc) * 2048;
        for (int o = tid; o < 2048; o += 256) {
            int nt = o >> 9, kp = (o >> 5) & 15, ln = o & 31;
            int tig = ln & 3, g = ln >> 2;
            int jl = nt * 8 + g;
            float4 v;
            v.x = s[(16 * kp + tig) * 36 + jl];
            v.y = s[(16 * kp + tig + 4) * 36 + jl];
            v.z = s[(16 * kp + 8 + tig) * 36 + jl];
            v.w = s[(16 * kp + 8 + tig + 4) * 36 + jl];
            dst[o] = v;
        }
    } else {
        int e = (b - 512) >> 5, jc = (b - 512) & 31;
        for (int i = tid; i < 2048; i += 256) {
            int rl = i >> 6, n4 = i & 63;
            float4 v = ((const float4*)(W2 + ((size_t)e * HID + jc * 32 + rl) * DM))[n4];
            *(float4*)&s[rl * 260 + n4 * 4] = tf32r4(v);
        }
        __syncthreads();
        float4* dst = (float4*)g_w2p + (size_t)(e * 32 + jc) * 2048;
        for (int o = tid; o < 2048; o += 256) {
            int nt = o >> 6, kp = (o >> 5) & 1, ln = o & 31;
            int tig = ln & 3, g = ln >> 2;
            int n = nt * 8 + g;
            float4 v;
            v.x = s[(16 * kp + tig) * 260 + n];
            v.y = s[(16 * kp + tig + 4) * 260 + n];
            v.z = s[(16 * kp + 8 + tig) * 260 + n];
            v.w = s[(16 * kp + 8 + tig + 4) * 260 + n];
            dst[o] = v;
        }
    }
}

// ---------------- kernel 1: router (bit-exact fp32 sequence, unchanged) ------
__global__ void router_kernel(const float* __restrict__ v0,
                              const float* __restrict__ v1,
                              const float* __restrict__ v2,
                              const float* __restrict__ rw,
                              const float* __restrict__ keys) {
    int vi   = blockIdx.y;
    int warp = threadIdx.x >> 5;
    int lane = threadIdx.x & 31;
    int tok  = blockIdx.x * 8 + warp;
    if (tok >= N_TOK) return;

    const float* vbase = (vi == 0) ? v0 : ((vi == 1) ? v1 : v2);
    const float* v = vbase + tok * DM;

    float4 a = ((const float4*)v)[lane];
    float4 b = ((const float4*)v)[lane + 32];

    float vv = wredsum(d4(a, a) + d4(b, b));

    const float* rwv = rw + (size_t)vi * NE * DM;
    float lg[NE];
#pragma unroll
    for (int e = 0; e < NE; e++) {
        const float4* kp = (const float4*)(keys + e * DM);
        const float4* rp = (const float4*)(rwv + e * DM);
        float4 k1 = kp[lane], k2 = kp[lane + 32];
        float4 r1 = rp[lane], r2 = rp[lane + 32];
        float dk = wredsum(d4(a, k1) + d4(b, k2));
        float dr = wredsum(d4(a, r1) + d4(b, r2));
        float kk = wredsum(d4(k1, k1) + d4(k2, k2));
        float sq = (vv + kk) - 2.0f * dk;
        lg[e] = (-sq) + dr;
    }

    if (lane == 0) {
        unsigned chosen = 0;
        float tv[TOPK];
        int   ti[TOPK];
#pragma unroll
        for (int k = 0; k < TOPK; k++) {
            float m = -1e30f; int mi = 0;
#pragma unroll
            for (int e = 0; e < NE; e++) {
                if (!((chosen >> e) & 1u) && lg[e] > m) { m = lg[e]; mi = e; }
            }
            tv[k] = m; ti[k] = mi; chosen |= (1u << mi);
        }
        float s = 0.f;
        float ex[TOPK];
#pragma unroll
        for (int k = 0; k < TOPK; k++) { ex[k] = expf(tv[k] - tv[0]); s += ex[k]; }
        float inv = 1.0f / s;
#pragma unroll
        for (int k = 0; k < TOPK; k++) {
            int ge  = vi * NE + ti[k];
            int pos = atomicAdd(&g_cnt[ge], 1);
            g_tok [ge * N_TOK + pos] = tok;
            g_gate[ge * N_TOK + pos] = ex[k] * inv;
        }
    }
}

// ---- kernel 2: grouped FFN, occ-2, single-barrier software pipeline --------
extern "C" __global__ void __launch_bounds__(256, 2)
ffn_kernel(const float* __restrict__ v0, const float* __restrict__ v1,
           const float* __restrict__ v2,
           const float* __restrict__ b1, const float* __restrict__ b2,
           float* __restrict__ out) {
    extern __shared__ float sm[];
    int tid = threadIdx.x, wid = tid >> 5, lane = tid & 31;
    int vi = blockIdx.z, e = blockIdx.y, g0 = vi * NE + e;
    int cnt = g_cnt[g0];
    int t0 = blockIdx.x * TM;
    if (t0 >= cnt) return;
    int rows = min(TM, cnt - t0);

    int*   s_tok  = (int*)&sm[TOK_F];
    float* s_gate = &sm[GATE_F];
    if (tid < TM) {
        int idx = t0 + tid;
        s_tok [tid] = (idx < cnt) ? g_tok [g0 * N_TOK + idx] : 0;
        s_gate[tid] = (idx < cnt) ? g_gate[g0 * N_TOK + idx] : 0.0f;
    }
    for (int i = tid; i < HID; i += 256) sm[B1_F + i] = b1[(size_t)e * HID + i];
    for (int i = tid; i < DM;  i += 256) sm[B2_F + i] = b2[(size_t)e * DM + i];
    __syncthreads();

    const float* V = (vi == 0) ? v0 : ((vi == 1) ? v1 : v2);

    // ---- gather X -> A-fragment-permuted smem (tf32-rna) ----
    for (int i = tid; i < TM * 64; i += 256) {
        int r = i >> 6, c4 = i & 63;
        float4 v = make_float4(0.f, 0.f, 0.f, 0.f);
        if (r < rows) v = tf32r4(((const float4*)(V + (size_t)s_tok[r] * DM))[c4]);
        int mt = r >> 4, pair = (r >> 3) & 1, gg2 = r & 7;
        int ks = c4 >> 1, q = pair + 2 * (c4 & 1);
        int base = ((mt * 32 + ks) * 32 + gg2 * 4) * 4 + q;
        sm[XP_F + base     ] = v.x;
        sm[XP_F + base + 4 ] = v.y;
        sm[XP_F + base + 8 ] = v.z;
        sm[XP_F + base + 12] = v.w;
    }
    __syncthreads();

    const uint4* XP  = (const uint4*)&sm[XP_F];
    const uint4* W1P = (const uint4*)g_w1p + (size_t)(e * 32) * 2048;
    const uint4* W2P = (const uint4*)g_w2p + (size_t)(e * 32) * 2048;
    const int gg = lane >> 2, cc = lane & 3;
    const int m1 = wid & 1, n1 = (wid >> 1) & 1, ch = wid >> 2;   // GEMM1 roles
    const int nb = wid * 4;                                       // GEMM2 role

    float4 acc[4][4];   // GEMM2: warp tile m64 x n32
#pragma unroll
    for (int i = 0; i < 4; i++)
#pragma unroll
        for (int j = 0; j < 4; j++) acc[i][j] = make_float4(0.f, 0.f, 0.f, 0.f);

    // ---- software pipeline: stage sc runs GEMM1(sc) then GEMM2(sc-1) ----
#pragma unroll 1
    for (int sc = 0; sc < 17; sc++) {
        // hoist GEMM2(sc-1)'s first W2 fragments: L2 latency hides under GEMM1
        uint4 wb0[4];
        if (sc > 0) {
            size_t jb0 = (size_t)((sc - 1) * 2) * 2048;
#pragma unroll
            for (int nt = 0; nt < 4; nt++)
                wb0[nt] = W2P[jb0 + (nb + nt) * 64 + lane];
        }

        if (sc < 16) {
            // ========= GEMM1: chunk jc = sc*2+ch, warp tile m32 x n16 ========
            int jc = sc * 2 + ch;
            float4 a1[2][2];
#pragma unroll
            for (int i = 0; i < 2; i++)
#pragma unroll
                for (int j = 0; j < 2; j++) a1[i][j] = make_float4(0.f, 0.f, 0.f, 0.f);
            const uint4* W1j = W1P + (size_t)jc * 2048 + lane;
            const int nb0 = (n1 * 2) * 512, nb1 = (n1 * 2 + 1) * 512;
            uint4 bb[2][2];
            bb[0][0] = W1j[nb0];      bb[0][1] = W1j[nb1];
            bb[1][0] = W1j[nb0 + 32]; bb[1][1] = W1j[nb1 + 32];
#pragma unroll
            for (int kp = 0; kp < 16; kp++) {
                uint4 bc0 = bb[kp & 1][0], bc1 = bb[kp & 1][1];
                if (kp + 2 < 16) {
                    bb[kp & 1][0] = W1j[nb0 + (kp + 2) * 32];
                    bb[kp & 1][1] = W1j[nb1 + (kp + 2) * 32];
                }
#pragma unroll
                for (int mt2 = 0; mt2 < 2; mt2++) {
                    int mt = 2 * m1 + mt2;
                    uint4 alo = XP[(mt * 32 + 2 * kp) * 32 + lane];
                    uint4 ahi = XP[(mt * 32 + 2 * kp + 1) * 32 + lane];
                    mma8(a1[mt2][0], alo, bc0.x, bc0.y);
                    mma8(a1[mt2][0], ahi, bc0.z, bc0.w);
                    mma8(a1[mt2][1], alo, bc1.x, bc1.y);
                    mma8(a1[mt2][1], ahi, bc1.z, bc1.w);
                }
            }
            // ---- bias + exact GELU -> H[sc&1] (A-frag order, tf32-rna) ----
            float* HB = &sm[HP_F + (sc & 1) * 4096];
#pragma unroll
            for (int mt2 = 0; mt2 < 2; mt2++) {
                int mt = 2 * m1 + mt2;
#pragma unroll
                for (int t = 0; t < 2; t++) {
                    int nt = n1 * 2 + t;
                    int ks = ch * 4 + nt;
                    int c0 = jc * 32 + nt * 8 + 2 * cc;
                    float bx = sm[B1_F + c0];
                    float by = sm[B1_F + c0 + 1];
                    float4 v = a1[mt2][t];
                    int base = ((mt * 8 + ks) * 32 + gg * 4) * 4
                             + 2 * (cc >> 1) + 8 * (cc & 1);
                    HB[base    ] = tf32r(gelu_exact(v.x + bx));
                    HB[base + 4] = tf32r(gelu_exact(v.y + by));
                    HB[base + 1] = tf32r(gelu_exact(v.z + bx));
                    HB[base + 5] = tf32r(gelu_exact(v.w + by));
                }
            }
        }

        if (sc > 0) {
            // ========= GEMM2: stage scp = sc-1, warp tile m64 x n32, K=64 ====
            int scp = sc - 1;
            const uint4* HPl = (const uint4*)&sm[HP_F + (scp & 1) * 4096];
            uint4 wb[2][4];
#pragma unroll
            for (int nt = 0; nt < 4; nt++) {
                wb[0][nt] = wb0[nt];   // hoisted, already landed
                wb[1][nt] = W2P[(size_t)(scp * 2) * 2048 + (nb + nt) * 64 + 32 + lane];
            }
#pragma unroll
            for (int kq = 0; kq < 4; kq++) {
                uint4 bc[4];
#pragma unroll
                for (int nt = 0; nt < 4; nt++) bc[nt] = wb[kq & 1][nt];
                if (kq + 2 < 4) {
                    size_t jb = (size_t)(scp * 2 + ((kq + 2) >> 1)) * 2048
                              + ((kq + 2) & 1) * 32;
#pragma unroll
                    for (int nt = 0; nt < 4; nt++)
                        wb[kq & 1][nt] = W2P[jb + (nb + nt) * 64 + lane];
                }
#pragma unroll
                for (int mt = 0; mt < 4; mt++) {
                    uint4 hlo = HPl[(mt * 8 + 2 * kq) * 32 + lane];
                    uint4 hhi = HPl[(mt * 8 + 2 * kq + 1) * 32 + lane];
#pragma unroll
                    for (int nt = 0; nt < 4; nt++) {
                        mma8(acc[mt][nt], hlo, bc[nt].x, bc[nt].y);
                        mma8(acc[mt][nt], hhi, bc[nt].z, bc[nt].w);
                    }
                }
            }
        }
        __syncthreads();   // stage boundary: H[sc&1] published, H[(sc-1)&1] consumed
    }

    // ---- epilogue: out[tok,:] += gate * (acc + b2), vector red ----
#pragma unroll
    for (int nt = 0; nt < 4; nt++) {
        int col = (wid * 4 + nt) * 8 + 2 * cc;
        float b2a = sm[B2_F + col], b2b = sm[B2_F + col + 1];
#pragma unroll
        for (int mt = 0; mt < 4; mt++) {
            float4 f = acc[mt][nt];
            int ra = mt * 16 + gg;
            int rb = ra + 8;
            if (ra < rows) {
                float gt = s_gate[ra];
                red2(out + (size_t)s_tok[ra] * DM + col,
                     gt * (f.x + b2a), gt * (f.y + b2b));
            }
            if (rb < rows) {
                float gt = s_gate[rb];
                red2(out + (size_t)s_tok[rb] * DM + col,
                     gt * (f.z + b2a), gt * (f.w + b2b));
            }
        }
    }
}

// ---------------- launch ----------------
extern "C" void kernel_launch(void* const* d_in, const int* in_sizes, int n_in,
                              void* d_out, int out_size) {
    const float* v0   = (const float*)d_in[0];
    const float* v1   = (const float*)d_in[1];
    const float* v2   = (const float*)d_in[2];
    const float* rw   = (const float*)d_in[3];
    const float* keys = (const float*)d_in[4];
    const float* W1   = (const float*)d_in[5];
    const float* b1   = (const float*)d_in[6];
    const float* W2   = (const float*)d_in[7];
    const float* b2   = (const float*)d_in[8];
    float* out = (float*)d_out;

    cudaFuncSetAttribute(ffn_kernel, cudaFuncAttributeMaxDynamicSharedMemorySize,
                         SMEM_BYTES);

    prep_kernel<<<1024, 256, 0, 0>>>(W1, W2, out);

    dim3 rgrid(N_TOK / 8, NVIEW, 1);
    router_kernel<<<rgrid, 256, 0, 0>>>(v0, v1, v2, rw, keys);

    dim3 fgrid(N_TOK / TM, NE, NVIEW);   // 128 x 16 x 3, most blocks exit early
    ffn_kernel<<<fgrid, 256, SMEM_BYTES, 0>>>(v0, v1, v2, b1, b2, out);
}

// round 11
// speedup vs baseline: 2.1797x; 1.5577x over previous
#include <cuda_runtime.h>
#include <cuda_fp16.h>
#include <math.h>
#include <cstdint>

#define N_TOK   8192
#define DM      256
#define NE      16
#define NVIEW   3
#define TOPK    4
#define HID     1024
#define TM      64

// ---- ffn smem layout (32-bit word indices) ----
#define XP_U    0           // X fp16 A-frag: [4mt][16ks][32lane][4] uints = 8192
#define HP_U    8192        // H fp16 A-frag: [4mt][4ks2][32lane][4] uints = 2048
#define B1_F    10240       // 1024 floats
#define B2_F    11264       // 256
#define TOK_F   11520       // 64 ints
#define GATE_F  11584       // 64
#define SMEM_WORDS 11648
#define SMEM_BYTES (SMEM_WORDS * 4)    // 46592 -> 2 blocks/SM easily

// ---------------- device scratch ----------------
__device__ int   g_cnt [NVIEW * NE];
__device__ int   g_tok [NVIEW * NE * N_TOK];
__device__ float g_gate[NVIEW * NE * N_TOK];
__device__ uint2 g_w1h [NE * 65536];   // W1 fp16 B-frag order, 8 MB
__device__ uint2 g_w2h [NE * 65536];   // W2 fp16 B-frag order, 8 MB

// ---------------- helpers ----------------
__device__ __forceinline__ uint32_t pk(float lo, float hi) {
    __half2 h = __floats2half2_rn(lo, hi);   // .x = lo (low 16 bits)
    return *reinterpret_cast<uint32_t*>(&h);
}
__device__ __forceinline__ float d4(float4 a, float4 b) {
    return a.x * b.x + a.y * b.y + a.z * b.z + a.w * b.w;
}
__device__ __forceinline__ float wredsum(float x) {
#pragma unroll
    for (int o = 16; o > 0; o >>= 1) x += __shfl_xor_sync(0xffffffffu, x, o);
    return x;
}
__device__ __forceinline__ float gelu_exact(float x) {
    return 0.5f * x * (1.0f + erff(x * 0.70710678118654752440f));
}
// m16n8k16 fp16 mma, fp32 accumulate: D += A*B
__device__ __forceinline__ void mma16(float4& d, const uint4& a,
                                      uint32_t b0, uint32_t b1) {
    asm volatile(
        "mma.sync.aligned.m16n8k16.row.col.f32.f16.f16.f32 "
        "{%0,%1,%2,%3}, {%4,%5,%6,%7}, {%8,%9}, {%0,%1,%2,%3};"
        : "+f"(d.x), "+f"(d.y), "+f"(d.z), "+f"(d.w)
        : "r"(a.x), "r"(a.y), "r"(a.z), "r"(a.w), "r"(b0), "r"(b1));
}
__device__ __forceinline__ void red2(float* p, float a, float b) {
    asm volatile("red.global.add.v2.f32 [%0], {%1, %2};"
                 :: "l"(p), "f"(a), "f"(b) : "memory");
}

// ------ kernel 0: prep (fp16-convert + B-frag permute weights; zero) --------
// W1 part (b<512): per (e, jc=32-col chunk): uint2[(ks*4+nt)*32+lane]
//   b0 = {W1[k0][n], W1[k0+1][n]}, b1 = {W1[k0+8][n], W1[k0+9][n]},
//   k0 = 16ks+2c, n = 8nt+g  (g=lane>>2, c=lane&3)
// W2 part (b>=512): per (e, sc, ks2): uint2[nt*32+lane], same frag formula
__global__ void prep_kernel(const float* __restrict__ W1,
                            const float* __restrict__ W2,
                            float* __restrict__ out) {
    __shared__ float s[9216];
    int tid = threadIdx.x, b = blockIdx.x;
    if (b == 0 && tid < NVIEW * NE) g_cnt[tid] = 0;
    if (b < 1024) {   // zero out: 524288 float4 over 1024 blocks
        float4* o4 = (float4*)out;
        int zb = b * 512 + tid;
        o4[zb]       = make_float4(0.f, 0.f, 0.f, 0.f);
        o4[zb + 256] = make_float4(0.f, 0.f, 0.f, 0.f);
    }
    if (b < 512) {
        int e = b >> 5, jc = b & 31;
        for (int i = tid; i < 2048; i += 256) {
            int d = i >> 3, j4 = i & 7;
            *(float4*)&s[d * 36 + j4 * 4] =
                ((const float4*)(W1 + ((size_t)e * DM + d) * HID + jc * 32))[j4];
        }
        __syncthreads();
        uint2* dst = g_w1h + (size_t)e * 65536 + jc * 2048;
        for (int o = tid; o < 2048; o += 256) {
            int lane = o & 31, nt = (o >> 5) & 3, ks = o >> 7;
            int g = lane >> 2, c = lane & 3;
            int n = nt * 8 + g, k0 = ks * 16 + 2 * c;
            uint2 val;
            val.x = pk(s[k0 * 36 + n],       s[(k0 + 1) * 36 + n]);
            val.y = pk(s[(k0 + 8) * 36 + n], s[(k0 + 9) * 36 + n]);
            dst[o] = val;
        }
    } else {
        int t = b - 512;
        int e = t >> 6, sc = (t >> 2) & 15, ks2 = t & 3;
        for (int i = tid; i < 1024; i += 256) {
            int rl = i >> 6, n4 = i & 63;
            *(float4*)&s[rl * 260 + n4 * 4] =
                ((const float4*)(W2 + ((size_t)e * HID + sc * 64 + ks2 * 16 + rl) * DM))[n4];
        }
        __syncthreads();
        uint2* dst = g_w2h + (size_t)e * 65536 + sc * 4096 + ks2 * 1024;
        for (int o = tid; o < 1024; o += 256) {
            int lane = o & 31, nt = o >> 5;
            int g = lane >> 2, c = lane & 3;
            int n = nt * 8 + g, k0 = 2 * c;
            uint2 val;
            val.x = pk(s[k0 * 260 + n],       s[(k0 + 1) * 260 + n]);
            val.y = pk(s[(k0 + 8) * 260 + n], s[(k0 + 9) * 260 + n]);
            dst[o] = val;
        }
    }
}

// ---------------- kernel 1: router (bit-exact fp32 sequence, unchanged) ------
__global__ void router_kernel(const float* __restrict__ v0,
                              const float* __restrict__ v1,
                              const float* __restrict__ v2,
                              const float* __restrict__ rw,
                              const float* __restrict__ keys) {
    int vi   = blockIdx.y;
    int warp = threadIdx.x >> 5;
    int lane = threadIdx.x & 31;
    int tok  = blockIdx.x * 8 + warp;
    if (tok >= N_TOK) return;

    const float* vbase = (vi == 0) ? v0 : ((vi == 1) ? v1 : v2);
    const float* v = vbase + tok * DM;

    float4 a = ((const float4*)v)[lane];
    float4 b = ((const float4*)v)[lane + 32];

    float vv = wredsum(d4(a, a) + d4(b, b));

    const float* rwv = rw + (size_t)vi * NE * DM;
    float lg[NE];
#pragma unroll
    for (int e = 0; e < NE; e++) {
        const float4* kp = (const float4*)(keys + e * DM);
        const float4* rp = (const float4*)(rwv + e * DM);
        float4 k1 = kp[lane], k2 = kp[lane + 32];
        float4 r1 = rp[lane], r2 = rp[lane + 32];
        float dk = wredsum(d4(a, k1) + d4(b, k2));
        float dr = wredsum(d4(a, r1) + d4(b, r2));
        float kk = wredsum(d4(k1, k1) + d4(k2, k2));
        float sq = (vv + kk) - 2.0f * dk;
        lg[e] = (-sq) + dr;
    }

    if (lane == 0) {
        unsigned chosen = 0;
        float tv[TOPK];
        int   ti[TOPK];
#pragma unroll
        for (int k = 0; k < TOPK; k++) {
            float m = -1e30f; int mi = 0;
#pragma unroll
            for (int e = 0; e < NE; e++) {
                if (!((chosen >> e) & 1u) && lg[e] > m) { m = lg[e]; mi = e; }
            }
            tv[k] = m; ti[k] = mi; chosen |= (1u << mi);
        }
        float s = 0.f;
        float ex[TOPK];
#pragma unroll
        for (int k = 0; k < TOPK; k++) { ex[k] = expf(tv[k] - tv[0]); s += ex[k]; }
        float inv = 1.0f / s;
#pragma unroll
        for (int k = 0; k < TOPK; k++) {
            int ge  = vi * NE + ti[k];
            int pos = atomicAdd(&g_cnt[ge], 1);
            g_tok [ge * N_TOK + pos] = tok;
            g_gate[ge * N_TOK + pos] = ex[k] * inv;
        }
    }
}

// ---- kernel 2: grouped FFN on fp16 mma (fp32 accumulate), occ-2 ------------
extern "C" __global__ void __launch_bounds__(256, 2)
ffn_kernel(const float* __restrict__ v0, const float* __restrict__ v1,
           const float* __restrict__ v2,
           const float* __restrict__ b1, const float* __restrict__ b2,
           float* __restrict__ out) {
    extern __shared__ float sm[];
    uint32_t* smu = (uint32_t*)sm;
    int tid = threadIdx.x, wid = tid >> 5, lane = tid & 31;
    int vi = blockIdx.z, e = blockIdx.y, g0 = vi * NE + e;
    int cnt = g_cnt[g0];
    int t0 = blockIdx.x * TM;
    if (t0 >= cnt) return;
    int rows = min(TM, cnt - t0);

    int*   s_tok  = (int*)&sm[TOK_F];
    float* s_gate = &sm[GATE_F];
    if (tid < TM) {
        int idx = t0 + tid;
        s_tok [tid] = (idx < cnt) ? g_tok [g0 * N_TOK + idx] : 0;
        s_gate[tid] = (idx < cnt) ? g_gate[g0 * N_TOK + idx] : 0.0f;
    }
    for (int i = tid; i < HID; i += 256) sm[B1_F + i] = b1[(size_t)e * HID + i];
    for (int i = tid; i < DM;  i += 256) sm[B2_F + i] = b2[(size_t)e * DM + i];
    __syncthreads();

    const float* V = (vi == 0) ? v0 : ((vi == 1) ? v1 : v2);

    // ---- gather X -> fp16 A-frag smem ----
    // token r: mt=r>>4, p=(r>>3)&1, g=r&7. col pair c2=2*c4: ks=c2>>3,
    // b=(c2&7)>>2, c=(c2&7)&3, reg q=p+2b. uint idx=((mt*16+ks)*32+g*4+c)*4+q
    for (int i = tid; i < TM * 64; i += 256) {
        int r = i >> 6, c4 = i & 63;
        float4 v = make_float4(0.f, 0.f, 0.f, 0.f);
        if (r < rows) v = ((const float4*)(V + (size_t)s_tok[r] * DM))[c4];
        uint32_t h01 = pk(v.x, v.y), h23 = pk(v.z, v.w);
        int mt = r >> 4, p = (r >> 3) & 1, g = r & 7;
        int c2 = 2 * c4, ks = c2 >> 3, c2in = c2 & 7;
        int q = p + 2 * (c2in >> 2), ca = c2in & 3;
        int base = ((mt * 16 + ks) * 32 + g * 4 + ca) * 4 + q;
        smu[XP_U + base]     = h01;
        smu[XP_U + base + 4] = h23;
    }
    __syncthreads();

    const uint4* XP  = (const uint4*)&smu[XP_U];
    const uint4* HPq = (const uint4*)&smu[HP_U];
    const uint2* W1B = g_w1h + (size_t)e * 65536;
    const uint2* W2B = g_w2h + (size_t)e * 65536;
    const int gg = lane >> 2, cc = lane & 3;
    const int m1 = wid & 1, n1 = (wid >> 1) & 1, ch = wid >> 2;   // GEMM1 roles
    const int nb = wid * 4;                                       // GEMM2 role

    float4 acc[4][4];   // GEMM2: warp tile m64 x n32
#pragma unroll
    for (int i = 0; i < 4; i++)
#pragma unroll
        for (int j = 0; j < 4; j++) acc[i][j] = make_float4(0.f, 0.f, 0.f, 0.f);

#pragma unroll 1
    for (int sc = 0; sc < 16; sc++) {
        // ========= GEMM1: chunk jc = sc*2+ch, warp tile m32 x n16, K=256 =====
        int jc = sc * 2 + ch;
        float4 a1[2][2];
#pragma unroll
        for (int i = 0; i < 2; i++)
#pragma unroll
            for (int j = 0; j < 2; j++) a1[i][j] = make_float4(0.f, 0.f, 0.f, 0.f);
        {
            const uint2* W1j = W1B + jc * 2048 + lane;
            const int nt0 = 2 * n1, nt1 = nt0 + 1;
            uint2 bb[2][2];
            bb[0][0] = W1j[nt0 * 32];        bb[0][1] = W1j[nt1 * 32];
            bb[1][0] = W1j[(4 + nt0) * 32];  bb[1][1] = W1j[(4 + nt1) * 32];
#pragma unroll
            for (int ks = 0; ks < 16; ks++) {
                uint2 bc0 = bb[ks & 1][0], bc1 = bb[ks & 1][1];
                if (ks + 2 < 16) {
                    bb[ks & 1][0] = W1j[((ks + 2) * 4 + nt0) * 32];
                    bb[ks & 1][1] = W1j[((ks + 2) * 4 + nt1) * 32];
                }
#pragma unroll
                for (int mt2 = 0; mt2 < 2; mt2++) {
                    int mt = 2 * m1 + mt2;
                    uint4 a = XP[(mt * 16 + ks) * 32 + lane];
                    mma16(a1[mt2][0], a, bc0.x, bc0.y);
                    mma16(a1[mt2][1], a, bc1.x, bc1.y);
                }
            }
        }

        // hoist GEMM2's W2 fragments now (independent of H; hides L2 latency)
        const uint2* W2s = W2B + sc * 4096;
        uint2 wb[2][4];
#pragma unroll
        for (int nt = 0; nt < 4; nt++) {
            wb[0][nt] = W2s[(nb + nt) * 32 + lane];
            wb[1][nt] = W2s[(32 + nb + nt) * 32 + lane];
        }

        __syncthreads();   // previous GEMM2 done reading H

        // ---- bias + exact GELU -> H fp16 A-frag (ks2 = 2ch+n1, q = p+2t) ----
        {
            int ks2 = 2 * ch + n1;
#pragma unroll
            for (int mt2 = 0; mt2 < 2; mt2++) {
                int mt = 2 * m1 + mt2;
                int rowbase = ((mt * 4 + ks2) * 32 + gg * 4 + cc) * 4;
#pragma unroll
                for (int t = 0; t < 2; t++) {
                    int nt = 2 * n1 + t;
                    int c0 = jc * 32 + nt * 8 + 2 * cc;
                    float bx = sm[B1_F + c0];
                    float by = sm[B1_F + c0 + 1];
                    float4 v = a1[mt2][t];
                    uint2 hv;
                    hv.x = pk(gelu_exact(v.x + bx), gelu_exact(v.y + by)); // row g
                    hv.y = pk(gelu_exact(v.z + bx), gelu_exact(v.w + by)); // row g+8
                    *(uint2*)&smu[HP_U + rowbase + 2 * t] = hv;
                }
            }
        }
        __syncthreads();   // H ready

        // ========= GEMM2: warp tile m64 x n32, K = 64 (4 k16-steps) ==========
#pragma unroll
        for (int ks2 = 0; ks2 < 4; ks2++) {
            uint2 bc[4];
#pragma unroll
            for (int nt = 0; nt < 4; nt++) bc[nt] = wb[ks2 & 1][nt];
            if (ks2 + 2 < 4) {
#pragma unroll
                for (int nt = 0; nt < 4; nt++)
                    wb[ks2 & 1][nt] = W2s[((ks2 + 2) * 32 + nb + nt) * 32 + lane];
            }
#pragma unroll
            for (int mt = 0; mt < 4; mt++) {
                uint4 h = HPq[(mt * 4 + ks2) * 32 + lane];
#pragma unroll
                for (int nt = 0; nt < 4; nt++)
                    mma16(acc[mt][nt], h, bc[nt].x, bc[nt].y);
            }
        }
    }

    // ---- epilogue: out[tok,:] += gate * (acc + b2), vector red ----
#pragma unroll
    for (int nt = 0; nt < 4; nt++) {
        int col = (nb + nt) * 8 + 2 * cc;
        float b2a = sm[B2_F + col], b2b = sm[B2_F + col + 1];
#pragma unroll
        for (int mt = 0; mt < 4; mt++) {
            float4 f = acc[mt][nt];
            int ra = mt * 16 + gg;
            int rb = ra + 8;
            if (ra < rows) {
                float gt = s_gate[ra];
                red2(out + (size_t)s_tok[ra] * DM + col,
                     gt * (f.x + b2a), gt * (f.y + b2b));
            }
            if (rb < rows) {
                float gt = s_gate[rb];
                red2(out + (size_t)s_tok[rb] * DM + col,
                     gt * (f.z + b2a), gt * (f.w + b2b));
            }
        }
    }
}

// ---------------- launch ----------------
extern "C" void kernel_launch(void* const* d_in, const int* in_sizes, int n_in,
                              void* d_out, int out_size) {
    const float* v0   = (const float*)d_in[0];
    const float* v1   = (const float*)d_in[1];
    const float* v2   = (const float*)d_in[2];
    const float* rw   = (const float*)d_in[3];
    const float* keys = (const float*)d_in[4];
    const float* W1   = (const float*)d_in[5];
    const float* b1   = (const float*)d_in[6];
    const float* W2   = (const float*)d_in[7];
    const float* b2   = (const float*)d_in[8];
    float* out = (float*)d_out;

    cudaFuncSetAttribute(ffn_kernel, cudaFuncAttributeMaxDynamicSharedMemorySize,
                         SMEM_BYTES);

    prep_kernel<<<1536, 256, 0, 0>>>(W1, W2, out);

    dim3 rgrid(N_TOK / 8, NVIEW, 1);
    router_kernel<<<rgrid, 256, 0, 0>>>(v0, v1, v2, rw, keys);

    dim3 fgrid(N_TOK / TM, NE, NVIEW);   // 128 x 16 x 3, most blocks exit early
    ffn_kernel<<<fgrid, 256, SMEM_BYTES, 0>>>(v0, v1, v2, b1, b2, out);
}

// round 12
// speedup vs baseline: 2.4026x; 1.1023x over previous
#include <cuda_runtime.h>
#include <cuda_fp16.h>
#include <math.h>
#include <cstdint>

#define N_TOK   8192
#define DM      256
#define NE      16
#define NVIEW   3
#define TOPK    4
#define HID     1024
#define TM      64

// ---- ffn smem layout (32-bit word indices) ----
#define XP_U    0           // X fp16 A-frag: [4mt][16ks][32lane][4] uints = 8192
#define HP_U    8192        // H fp16 A-frag DOUBLE buffer: 2 x 2048 uints = 4096
#define B1_F    12288       // 1024 floats
#define B2_F    13312       // 256
#define TOK_F   13568       // 64 ints
#define GATE_F  13632       // 64
#define SMEM_WORDS 13696
#define SMEM_BYTES (SMEM_WORDS * 4)    // 54784 -> 2 blocks/SM

// ---------------- device scratch ----------------
__device__ int   g_cnt [NVIEW * NE];
__device__ int   g_tok [NVIEW * NE * N_TOK];
__device__ float g_gate[NVIEW * NE * N_TOK];
__device__ uint2 g_w1h [NE * 65536];   // W1 fp16 B-frag order, 8 MB
__device__ uint2 g_w2h [NE * 65536];   // W2 fp16 B-frag order, 8 MB

// ---------------- helpers ----------------
__device__ __forceinline__ uint32_t pk(float lo, float hi) {
    __half2 h = __floats2half2_rn(lo, hi);   // .x = lo (low 16 bits)
    return *reinterpret_cast<uint32_t*>(&h);
}
__device__ __forceinline__ float d4(float4 a, float4 b) {
    return a.x * b.x + a.y * b.y + a.z * b.z + a.w * b.w;
}
__device__ __forceinline__ float wredsum(float x) {
#pragma unroll
    for (int o = 16; o > 0; o >>= 1) x += __shfl_xor_sync(0xffffffffu, x, o);
    return x;
}
__device__ __forceinline__ float gelu_exact(float x) {
    return 0.5f * x * (1.0f + erff(x * 0.70710678118654752440f));
}
// m16n8k16 fp16 mma, fp32 accumulate: D += A*B
__device__ __forceinline__ void mma16(float4& d, const uint4& a,
                                      uint32_t b0, uint32_t b1) {
    asm volatile(
        "mma.sync.aligned.m16n8k16.row.col.f32.f16.f16.f32 "
        "{%0,%1,%2,%3}, {%4,%5,%6,%7}, {%8,%9}, {%0,%1,%2,%3};"
        : "+f"(d.x), "+f"(d.y), "+f"(d.z), "+f"(d.w)
        : "r"(a.x), "r"(a.y), "r"(a.z), "r"(a.w), "r"(b0), "r"(b1));
}
__device__ __forceinline__ void red2(float* p, float a, float b) {
    asm volatile("red.global.add.v2.f32 [%0], {%1, %2};"
                 :: "l"(p), "f"(a), "f"(b) : "memory");
}

// ------ kernel 0: prep (fp16-convert + B-frag permute weights; zero) --------
__global__ void prep_kernel(const float* __restrict__ W1,
                            const float* __restrict__ W2,
                            float* __restrict__ out) {
    __shared__ float s[9216];
    int tid = threadIdx.x, b = blockIdx.x;
    if (b == 0 && tid < NVIEW * NE) g_cnt[tid] = 0;
    if (b < 1024) {   // zero out: 524288 float4 over 1024 blocks
        float4* o4 = (float4*)out;
        int zb = b * 512 + tid;
        o4[zb]       = make_float4(0.f, 0.f, 0.f, 0.f);
        o4[zb + 256] = make_float4(0.f, 0.f, 0.f, 0.f);
    }
    if (b < 512) {
        int e = b >> 5, jc = b & 31;
        for (int i = tid; i < 2048; i += 256) {
            int d = i >> 3, j4 = i & 7;
            *(float4*)&s[d * 36 + j4 * 4] =
                ((const float4*)(W1 + ((size_t)e * DM + d) * HID + jc * 32))[j4];
        }
        __syncthreads();
        uint2* dst = g_w1h + (size_t)e * 65536 + jc * 2048;
        for (int o = tid; o < 2048; o += 256) {
            int lane = o & 31, nt = (o >> 5) & 3, ks = o >> 7;
            int g = lane >> 2, c = lane & 3;
            int n = nt * 8 + g, k0 = ks * 16 + 2 * c;
            uint2 val;
            val.x = pk(s[k0 * 36 + n],       s[(k0 + 1) * 36 + n]);
            val.y = pk(s[(k0 + 8) * 36 + n], s[(k0 + 9) * 36 + n]);
            dst[o] = val;
        }
    } else {
        int t = b - 512;
        int e = t >> 6, sc = (t >> 2) & 15, ks2 = t & 3;
        for (int i = tid; i < 1024; i += 256) {
            int rl = i >> 6, n4 = i & 63;
            *(float4*)&s[rl * 260 + n4 * 4] =
                ((const float4*)(W2 + ((size_t)e * HID + sc * 64 + ks2 * 16 + rl) * DM))[n4];
        }
        __syncthreads();
        uint2* dst = g_w2h + (size_t)e * 65536 + sc * 4096 + ks2 * 1024;
        for (int o = tid; o < 1024; o += 256) {
            int lane = o & 31, nt = o >> 5;
            int g = lane >> 2, c = lane & 3;
            int n = nt * 8 + g, k0 = 2 * c;
            uint2 val;
            val.x = pk(s[k0 * 260 + n],       s[(k0 + 1) * 260 + n]);
            val.y = pk(s[(k0 + 8) * 260 + n], s[(k0 + 9) * 260 + n]);
            dst[o] = val;
        }
    }
}

// ---------------- kernel 1: router (bit-exact fp32 sequence, unchanged) ------
__global__ void router_kernel(const float* __restrict__ v0,
                              const float* __restrict__ v1,
                              const float* __restrict__ v2,
                              const float* __restrict__ rw,
                              const float* __restrict__ keys) {
    int vi   = blockIdx.y;
    int warp = threadIdx.x >> 5;
    int lane = threadIdx.x & 31;
    int tok  = blockIdx.x * 8 + warp;
    if (tok >= N_TOK) return;

    const float* vbase = (vi == 0) ? v0 : ((vi == 1) ? v1 : v2);
    const float* v = vbase + tok * DM;

    float4 a = ((const float4*)v)[lane];
    float4 b = ((const float4*)v)[lane + 32];

    float vv = wredsum(d4(a, a) + d4(b, b));

    const float* rwv = rw + (size_t)vi * NE * DM;
    float lg[NE];
#pragma unroll
    for (int e = 0; e < NE; e++) {
        const float4* kp = (const float4*)(keys + e * DM);
        const float4* rp = (const float4*)(rwv + e * DM);
        float4 k1 = kp[lane], k2 = kp[lane + 32];
        float4 r1 = rp[lane], r2 = rp[lane + 32];
        float dk = wredsum(d4(a, k1) + d4(b, k2));
        float dr = wredsum(d4(a, r1) + d4(b, r2));
        float kk = wredsum(d4(k1, k1) + d4(k2, k2));
        float sq = (vv + kk) - 2.0f * dk;
        lg[e] = (-sq) + dr;
    }

    if (lane == 0) {
        unsigned chosen = 0;
        float tv[TOPK];
        int   ti[TOPK];
#pragma unroll
        for (int k = 0; k < TOPK; k++) {
            float m = -1e30f; int mi = 0;
#pragma unroll
            for (int e = 0; e < NE; e++) {
                if (!((chosen >> e) & 1u) && lg[e] > m) { m = lg[e]; mi = e; }
            }
            tv[k] = m; ti[k] = mi; chosen |= (1u << mi);
        }
        float s = 0.f;
        float ex[TOPK];
#pragma unroll
        for (int k = 0; k < TOPK; k++) { ex[k] = expf(tv[k] - tv[0]); s += ex[k]; }
        float inv = 1.0f / s;
#pragma unroll
        for (int k = 0; k < TOPK; k++) {
            int ge  = vi * NE + ti[k];
            int pos = atomicAdd(&g_cnt[ge], 1);
            g_tok [ge * N_TOK + pos] = tok;
            g_gate[ge * N_TOK + pos] = ex[k] * inv;
        }
    }
}

// ---- kernel 2: grouped FFN on fp16 mma, single barrier per superchunk ------
extern "C" __global__ void __launch_bounds__(256, 2)
ffn_kernel(const float* __restrict__ v0, const float* __restrict__ v1,
           const float* __restrict__ v2,
           const float* __restrict__ b1, const float* __restrict__ b2,
           float* __restrict__ out) {
    extern __shared__ float sm[];
    uint32_t* smu = (uint32_t*)sm;
    int tid = threadIdx.x, wid = tid >> 5, lane = tid & 31;
    int vi = blockIdx.z, e = blockIdx.y, g0 = vi * NE + e;
    int cnt = g_cnt[g0];
    int t0 = blockIdx.x * TM;
    if (t0 >= cnt) return;
    int rows = min(TM, cnt - t0);

    int*   s_tok  = (int*)&sm[TOK_F];
    float* s_gate = &sm[GATE_F];
    if (tid < TM) {
        int idx = t0 + tid;
        s_tok [tid] = (idx < cnt) ? g_tok [g0 * N_TOK + idx] : 0;
        s_gate[tid] = (idx < cnt) ? g_gate[g0 * N_TOK + idx] : 0.0f;
    }
    for (int i = tid; i < HID; i += 256) sm[B1_F + i] = b1[(size_t)e * HID + i];
    for (int i = tid; i < DM;  i += 256) sm[B2_F + i] = b2[(size_t)e * DM + i];
    __syncthreads();

    const float* V = (vi == 0) ? v0 : ((vi == 1) ? v1 : v2);

    // ---- gather X -> fp16 A-frag smem ----
    for (int i = tid; i < TM * 64; i += 256) {
        int r = i >> 6, c4 = i & 63;
        float4 v = make_float4(0.f, 0.f, 0.f, 0.f);
        if (r < rows) v = ((const float4*)(V + (size_t)s_tok[r] * DM))[c4];
        uint32_t h01 = pk(v.x, v.y), h23 = pk(v.z, v.w);
        int mt = r >> 4, p = (r >> 3) & 1, g = r & 7;
        int c2 = 2 * c4, ks = c2 >> 3, c2in = c2 & 7;
        int q = p + 2 * (c2in >> 2), ca = c2in & 3;
        int base = ((mt * 16 + ks) * 32 + g * 4 + ca) * 4 + q;
        smu[XP_U + base]     = h01;
        smu[XP_U + base + 4] = h23;
    }
    __syncthreads();

    const uint4* XP  = (const uint4*)&smu[XP_U];
    const uint2* W1B = g_w1h + (size_t)e * 65536;
    const uint2* W2B = g_w2h + (size_t)e * 65536;
    const int gg = lane >> 2, cc = lane & 3;
    const int m1 = wid & 1, n1 = (wid >> 1) & 1, ch = wid >> 2;   // GEMM1 roles
    const int nb = wid * 4;                                       // GEMM2 role

    float4 acc[4][4];   // GEMM2: warp tile m64 x n32
#pragma unroll
    for (int i = 0; i < 4; i++)
#pragma unroll
        for (int j = 0; j < 4; j++) acc[i][j] = make_float4(0.f, 0.f, 0.f, 0.f);

#pragma unroll 1
    for (int sc = 0; sc < 16; sc++) {
        // ========= GEMM1: chunk jc = sc*2+ch, warp tile m32 x n16, K=256 =====
        int jc = sc * 2 + ch;
        float4 a1[2][2];
#pragma unroll
        for (int i = 0; i < 2; i++)
#pragma unroll
            for (int j = 0; j < 2; j++) a1[i][j] = make_float4(0.f, 0.f, 0.f, 0.f);
        {
            const uint2* W1j = W1B + jc * 2048 + lane;
            const int nt0 = 2 * n1, nt1 = nt0 + 1;
            uint2 bb[2][2];
            bb[0][0] = W1j[nt0 * 32];        bb[0][1] = W1j[nt1 * 32];
            bb[1][0] = W1j[(4 + nt0) * 32];  bb[1][1] = W1j[(4 + nt1) * 32];
#pragma unroll
            for (int ks = 0; ks < 16; ks++) {
                uint2 bc0 = bb[ks & 1][0], bc1 = bb[ks & 1][1];
                if (ks + 2 < 16) {
                    bb[ks & 1][0] = W1j[((ks + 2) * 4 + nt0) * 32];
                    bb[ks & 1][1] = W1j[((ks + 2) * 4 + nt1) * 32];
                }
#pragma unroll
                for (int mt2 = 0; mt2 < 2; mt2++) {
                    int mt = 2 * m1 + mt2;
                    uint4 a = XP[(mt * 16 + ks) * 32 + lane];
                    mma16(a1[mt2][0], a, bc0.x, bc0.y);
                    mma16(a1[mt2][1], a, bc1.x, bc1.y);
                }
            }
        }

        // hoist GEMM2's W2 fragments (independent of H; hides L2 latency)
        const uint2* W2s = W2B + sc * 4096;
        uint2 wb[2][4];
#pragma unroll
        for (int nt = 0; nt < 4; nt++) {
            wb[0][nt] = W2s[(nb + nt) * 32 + lane];
            wb[1][nt] = W2s[(32 + nb + nt) * 32 + lane];
        }

        // ---- bias + exact GELU -> H[sc&1] fp16 A-frag (no barrier needed:
        //      any warp still reading H[sc&1] would be in GEMM2(sc-2), which
        //      all warps finished before passing BAR(sc-1)) ----
        uint32_t* HB = &smu[HP_U + (sc & 1) * 2048];
        {
            int ks2 = 2 * ch + n1;
#pragma unroll
            for (int mt2 = 0; mt2 < 2; mt2++) {
                int mt = 2 * m1 + mt2;
                int rowbase = ((mt * 4 + ks2) * 32 + gg * 4 + cc) * 4;
#pragma unroll
                for (int t = 0; t < 2; t++) {
                    int nt = 2 * n1 + t;
                    int c0 = jc * 32 + nt * 8 + 2 * cc;
                    float bx = sm[B1_F + c0];
                    float by = sm[B1_F + c0 + 1];
                    float4 v = a1[mt2][t];
                    uint2 hv;
                    hv.x = pk(gelu_exact(v.x + bx), gelu_exact(v.y + by)); // row g
                    hv.y = pk(gelu_exact(v.z + bx), gelu_exact(v.w + by)); // row g+8
                    *(uint2*)&HB[rowbase + 2 * t] = hv;
                }
            }
        }
        __syncthreads();   // single stage barrier: H[sc&1] ready

        // ========= GEMM2: warp tile m64 x n32, K = 64 (4 k16-steps) ==========
        const uint4* HPq = (const uint4*)HB;
#pragma unroll
        for (int ks2 = 0; ks2 < 4; ks2++) {
            uint2 bc[4];
#pragma unroll
            for (int nt = 0; nt < 4; nt++) bc[nt] = wb[ks2 & 1][nt];
            if (ks2 + 2 < 4) {
#pragma unroll
                for (int nt = 0; nt < 4; nt++)
                    wb[ks2 & 1][nt] = W2s[((ks2 + 2) * 32 + nb + nt) * 32 + lane];
            }
#pragma unroll
            for (int mt = 0; mt < 4; mt++) {
                uint4 h = HPq[(mt * 4 + ks2) * 32 + lane];
#pragma unroll
                for (int nt = 0; nt < 4; nt++)
                    mma16(acc[mt][nt], h, bc[nt].x, bc[nt].y);
            }
        }
    }

    // ---- epilogue: out[tok,:] += gate * (acc + b2), vector red ----
#pragma unroll
    for (int nt = 0; nt < 4; nt++) {
        int col = (nb + nt) * 8 + 2 * cc;
        float b2a = sm[B2_F + col], b2b = sm[B2_F + col + 1];
#pragma unroll
        for (int mt = 0; mt < 4; mt++) {
            float4 f = acc[mt][nt];
            int ra = mt * 16 + gg;
            int rb = ra + 8;
            if (ra < rows) {
                float gt = s_gate[ra];
                red2(out + (size_t)s_tok[ra] * DM + col,
                     gt * (f.x + b2a), gt * (f.y + b2b));
            }
            if (rb < rows) {
                float gt = s_gate[rb];
                red2(out + (size_t)s_tok[rb] * DM + col,
                     gt * (f.z + b2a), gt * (f.w + b2b));
            }
        }
    }
}

// ---------------- launch ----------------
extern "C" void kernel_launch(void* const* d_in, const int* in_sizes, int n_in,
                              void* d_out, int out_size) {
    const float* v0   = (const float*)d_in[0];
    const float* v1   = (const float*)d_in[1];
    const float* v2   = (const float*)d_in[2];
    const float* rw   = (const float*)d_in[3];
    const float* keys = (const float*)d_in[4];
    const float* W1   = (const float*)d_in[5];
    const float* b1   = (const float*)d_in[6];
    const float* W2   = (const float*)d_in[7];
    const float* b2   = (const float*)d_in[8];
    float* out = (float*)d_out;

    cudaFuncSetAttribute(ffn_kernel, cudaFuncAttributeMaxDynamicSharedMemorySize,
                         SMEM_BYTES);

    prep_kernel<<<1536, 256, 0, 0>>>(W1, W2, out);

    dim3 rgrid(N_TOK / 8, NVIEW, 1);
    router_kernel<<<rgrid, 256, 0, 0>>>(v0, v1, v2, rw, keys);

    dim3 fgrid(N_TOK / TM, NE, NVIEW);   // 128 x 16 x 3, most blocks exit early
    ffn_kernel<<<fgrid, 256, SMEM_BYTES, 0>>>(v0, v1, v2, b1, b2, out);
}

// round 13
// speedup vs baseline: 2.4209x; 1.0076x over previous
#include <cuda_runtime.h>
#include <cuda_fp16.h>
#include <math.h>
#include <cstdint>

#define N_TOK   8192
#define DM      256
#define NE      16
#define NVIEW   3
#define TOPK    4
#define HID     1024
#define TM      64

// ---- ffn smem layout (32-bit word indices) ----
#define XP_U    0           // X fp16 A-frag: [4mt][16ks][32lane][4] uints = 8192
#define HP_U    8192        // H fp16 A-frag QUAD buffer: 4 x 2048 uints = 8192
#define B1_F    16384       // 1024 floats
#define B2_F    17408       // 256
#define TOK_F   17664       // 64 ints
#define GATE_F  17728       // 64
#define SMEM_WORDS 17792
#define SMEM_BYTES (SMEM_WORDS * 4)    // 71168 -> 2 blocks/SM

// ---------------- device scratch ----------------
__device__ int   g_cnt [NVIEW * NE];
__device__ int   g_tok [NVIEW * NE * N_TOK];
__device__ float g_gate[NVIEW * NE * N_TOK];
__device__ uint2 g_w1h [NE * 65536];   // W1 fp16 B-frag order, 8 MB
__device__ uint2 g_w2h [NE * 65536];   // W2 fp16 B-frag order, 8 MB

// ---------------- helpers ----------------
__device__ __forceinline__ uint32_t pk(float lo, float hi) {
    __half2 h = __floats2half2_rn(lo, hi);   // .x = lo (low 16 bits)
    return *reinterpret_cast<uint32_t*>(&h);
}
__device__ __forceinline__ float d4(float4 a, float4 b) {
    return a.x * b.x + a.y * b.y + a.z * b.z + a.w * b.w;
}
__device__ __forceinline__ float wredsum(float x) {
#pragma unroll
    for (int o = 16; o > 0; o >>= 1) x += __shfl_xor_sync(0xffffffffu, x, o);
    return x;
}
__device__ __forceinline__ float gelu_exact(float x) {
    return 0.5f * x * (1.0f + erff(x * 0.70710678118654752440f));
}
// m16n8k16 fp16 mma, fp32 accumulate: D += A*B
__device__ __forceinline__ void mma16(float4& d, const uint4& a,
                                      uint32_t b0, uint32_t b1) {
    asm volatile(
        "mma.sync.aligned.m16n8k16.row.col.f32.f16.f16.f32 "
        "{%0,%1,%2,%3}, {%4,%5,%6,%7}, {%8,%9}, {%0,%1,%2,%3};"
        : "+f"(d.x), "+f"(d.y), "+f"(d.z), "+f"(d.w)
        : "r"(a.x), "r"(a.y), "r"(a.z), "r"(a.w), "r"(b0), "r"(b1));
}
__device__ __forceinline__ void red2(float* p, float a, float b) {
    asm volatile("red.global.add.v2.f32 [%0], {%1, %2};"
                 :: "l"(p), "f"(a), "f"(b) : "memory");
}

// ---- merged kernel 0: prep (blocks 0..1535) + router (blocks 1536..4607) ---
// g_cnt must be zeroed by a prior memset (done in kernel_launch).
__global__ void prep_router_kernel(const float* __restrict__ W1,
                                   const float* __restrict__ W2,
                                   const float* __restrict__ v0,
                                   const float* __restrict__ v1,
                                   const float* __restrict__ v2,
                                   const float* __restrict__ rw,
                                   const float* __restrict__ keys,
                                   float* __restrict__ out) {
    __shared__ float s[9216];
    int tid = threadIdx.x, b = blockIdx.x;

    if (b < 1536) {
        // ---------------- prep part ----------------
        if (b < 1024) {   // zero out: 524288 float4 over 1024 blocks
            float4* o4 = (float4*)out;
            int zb = b * 512 + tid;
            o4[zb]       = make_float4(0.f, 0.f, 0.f, 0.f);
            o4[zb + 256] = make_float4(0.f, 0.f, 0.f, 0.f);
        }
        if (b < 512) {
            int e = b >> 5, jc = b & 31;
            for (int i = tid; i < 2048; i += 256) {
                int d = i >> 3, j4 = i & 7;
                *(float4*)&s[d * 36 + j4 * 4] =
                    ((const float4*)(W1 + ((size_t)e * DM + d) * HID + jc * 32))[j4];
            }
            __syncthreads();
            uint2* dst = g_w1h + (size_t)e * 65536 + jc * 2048;
            for (int o = tid; o < 2048; o += 256) {
                int lane = o & 31, nt = (o >> 5) & 3, ks = o >> 7;
                int g = lane >> 2, c = lane & 3;
                int n = nt * 8 + g, k0 = ks * 16 + 2 * c;
                uint2 val;
                val.x = pk(s[k0 * 36 + n],       s[(k0 + 1) * 36 + n]);
                val.y = pk(s[(k0 + 8) * 36 + n], s[(k0 + 9) * 36 + n]);
                dst[o] = val;
            }
        } else {
            int t = b - 512;
            int e = t >> 6, sc = (t >> 2) & 15, ks2 = t & 3;
            for (int i = tid; i < 1024; i += 256) {
                int rl = i >> 6, n4 = i & 63;
                *(float4*)&s[rl * 260 + n4 * 4] =
                    ((const float4*)(W2 + ((size_t)e * HID + sc * 64 + ks2 * 16 + rl) * DM))[n4];
            }
            __syncthreads();
            uint2* dst = g_w2h + (size_t)e * 65536 + sc * 4096 + ks2 * 1024;
            for (int o = tid; o < 1024; o += 256) {
                int lane = o & 31, nt = o >> 5;
                int g = lane >> 2, c = lane & 3;
                int n = nt * 8 + g, k0 = 2 * c;
                uint2 val;
                val.x = pk(s[k0 * 260 + n],       s[(k0 + 1) * 260 + n]);
                val.y = pk(s[(k0 + 8) * 260 + n], s[(k0 + 9) * 260 + n]);
                dst[o] = val;
            }
        }
        return;
    }

    // ---------------- router part (bit-exact fp32 sequence) ----------------
    int rb   = b - 1536;
    int vi   = rb >> 10;
    int bx   = rb & 1023;
    int warp = tid >> 5;
    int lane = tid & 31;
    int tok  = bx * 8 + warp;

    const float* vbase = (vi == 0) ? v0 : ((vi == 1) ? v1 : v2);
    const float* v = vbase + tok * DM;

    float4 a = ((const float4*)v)[lane];
    float4 bb = ((const float4*)v)[lane + 32];

    float vv = wredsum(d4(a, a) + d4(bb, bb));

    const float* rwv = rw + (size_t)vi * NE * DM;
    float lg[NE];
#pragma unroll
    for (int e = 0; e < NE; e++) {
        const float4* kp = (const float4*)(keys + e * DM);
        const float4* rp = (const float4*)(rwv + e * DM);
        float4 k1 = kp[lane], k2 = kp[lane + 32];
        float4 r1 = rp[lane], r2 = rp[lane + 32];
        float dk = wredsum(d4(a, k1) + d4(bb, k2));
        float dr = wredsum(d4(a, r1) + d4(bb, r2));
        float kk = wredsum(d4(k1, k1) + d4(k2, k2));
        float sq = (vv + kk) - 2.0f * dk;
        lg[e] = (-sq) + dr;
    }

    if (lane == 0) {
        unsigned chosen = 0;
        float tv[TOPK];
        int   ti[TOPK];
#pragma unroll
        for (int k = 0; k < TOPK; k++) {
            float m = -1e30f; int mi = 0;
#pragma unroll
            for (int e = 0; e < NE; e++) {
                if (!((chosen >> e) & 1u) && lg[e] > m) { m = lg[e]; mi = e; }
            }
            tv[k] = m; ti[k] = mi; chosen |= (1u << mi);
        }
        float sum = 0.f;
        float ex[TOPK];
#pragma unroll
        for (int k = 0; k < TOPK; k++) { ex[k] = expf(tv[k] - tv[0]); sum += ex[k]; }
        float inv = 1.0f / sum;
#pragma unroll
        for (int k = 0; k < TOPK; k++) {
            int ge  = vi * NE + ti[k];
            int pos = atomicAdd(&g_cnt[ge], 1);
            g_tok [ge * N_TOK + pos] = tok;
            g_gate[ge * N_TOK + pos] = ex[k] * inv;
        }
    }
}

// ---- GEMM2 inner step: acc += H(stage) @ W2(stage), K=64 -------------------
__device__ __forceinline__ void gemm2_step(float4 (&acc)[4][4],
                                           const uint4* HPq, const uint2* W2s,
                                           uint2 (&wb)[2][4],
                                           int nb, int lane, bool preloaded) {
    if (!preloaded) {
#pragma unroll
        for (int nt = 0; nt < 4; nt++) {
            wb[0][nt] = W2s[(nb + nt) * 32 + lane];
            wb[1][nt] = W2s[(32 + nb + nt) * 32 + lane];
        }
    }
#pragma unroll
    for (int ks2 = 0; ks2 < 4; ks2++) {
        uint2 bc[4];
#pragma unroll
        for (int nt = 0; nt < 4; nt++) bc[nt] = wb[ks2 & 1][nt];
        if (ks2 + 2 < 4) {
#pragma unroll
            for (int nt = 0; nt < 4; nt++)
                wb[ks2 & 1][nt] = W2s[((ks2 + 2) * 32 + nb + nt) * 32 + lane];
        }
#pragma unroll
        for (int mt = 0; mt < 4; mt++) {
            uint4 h = HPq[(mt * 4 + ks2) * 32 + lane];
#pragma unroll
            for (int nt = 0; nt < 4; nt++)
                mma16(acc[mt][nt], h, bc[nt].x, bc[nt].y);
        }
    }
}

// ---- kernel 1: grouped FFN on fp16 mma, 8 barriers (quad-buffered H) -------
extern "C" __global__ void __launch_bounds__(256, 2)
ffn_kernel(const float* __restrict__ v0, const float* __restrict__ v1,
           const float* __restrict__ v2,
           const float* __restrict__ b1, const float* __restrict__ b2,
           float* __restrict__ out) {
    extern __shared__ float sm[];
    uint32_t* smu = (uint32_t*)sm;
    int tid = threadIdx.x, wid = tid >> 5, lane = tid & 31;
    int vi = blockIdx.z, e = blockIdx.y, g0 = vi * NE + e;
    int cnt = g_cnt[g0];
    int t0 = blockIdx.x * TM;
    if (t0 >= cnt) return;
    int rows = min(TM, cnt - t0);

    int*   s_tok  = (int*)&sm[TOK_F];
    float* s_gate = &sm[GATE_F];
    if (tid < TM) {
        int idx = t0 + tid;
        s_tok [tid] = (idx < cnt) ? g_tok [g0 * N_TOK + idx] : 0;
        s_gate[tid] = (idx < cnt) ? g_gate[g0 * N_TOK + idx] : 0.0f;
    }
    for (int i = tid; i < HID; i += 256) sm[B1_F + i] = b1[(size_t)e * HID + i];
    for (int i = tid; i < DM;  i += 256) sm[B2_F + i] = b2[(size_t)e * DM + i];
    __syncthreads();

    const float* V = (vi == 0) ? v0 : ((vi == 1) ? v1 : v2);

    // ---- gather X -> fp16 A-frag smem ----
    for (int i = tid; i < TM * 64; i += 256) {
        int r = i >> 6, c4 = i & 63;
        float4 v = make_float4(0.f, 0.f, 0.f, 0.f);
        if (r < rows) v = ((const float4*)(V + (size_t)s_tok[r] * DM))[c4];
        uint32_t h01 = pk(v.x, v.y), h23 = pk(v.z, v.w);
        int mt = r >> 4, p = (r >> 3) & 1, g = r & 7;
        int c2 = 2 * c4, ks = c2 >> 3, c2in = c2 & 7;
        int q = p + 2 * (c2in >> 2), ca = c2in & 3;
        int base = ((mt * 16 + ks) * 32 + g * 4 + ca) * 4 + q;
        smu[XP_U + base]     = h01;
        smu[XP_U + base + 4] = h23;
    }
    __syncthreads();

    const uint4* XP  = (const uint4*)&smu[XP_U];
    const uint2* W1B = g_w1h + (size_t)e * 65536;
    const uint2* W2B = g_w2h + (size_t)e * 65536;
    const int gg = lane >> 2, cc = lane & 3;
    const int m1 = wid & 1, n1 = (wid >> 1) & 1, ch = wid >> 2;   // GEMM1 roles
    const int nb = wid * 4;                                       // GEMM2 role

    float4 acc[4][4];   // GEMM2: warp tile m64 x n32
#pragma unroll
    for (int i = 0; i < 4; i++)
#pragma unroll
        for (int j = 0; j < 4; j++) acc[i][j] = make_float4(0.f, 0.f, 0.f, 0.f);

#pragma unroll 1
    for (int t = 0; t < 8; t++) {
        // ===== two superchunks of GEMM1 + GELU into quad-buffered H =========
#pragma unroll
        for (int h2 = 0; h2 < 2; h2++) {
            int sc = 2 * t + h2;
            int jc = sc * 2 + ch;
            float4 a1[2][2];
#pragma unroll
            for (int i = 0; i < 2; i++)
#pragma unroll
                for (int j = 0; j < 2; j++) a1[i][j] = make_float4(0.f, 0.f, 0.f, 0.f);
            {
                const uint2* W1j = W1B + jc * 2048 + lane;
                const int nt0 = 2 * n1, nt1 = nt0 + 1;
                uint2 bb[2][2];
                bb[0][0] = W1j[nt0 * 32];        bb[0][1] = W1j[nt1 * 32];
                bb[1][0] = W1j[(4 + nt0) * 32];  bb[1][1] = W1j[(4 + nt1) * 32];
#pragma unroll
                for (int ks = 0; ks < 16; ks++) {
                    uint2 bc0 = bb[ks & 1][0], bc1 = bb[ks & 1][1];
                    if (ks + 2 < 16) {
                        bb[ks & 1][0] = W1j[((ks + 2) * 4 + nt0) * 32];
                        bb[ks & 1][1] = W1j[((ks + 2) * 4 + nt1) * 32];
                    }
#pragma unroll
                    for (int mt2 = 0; mt2 < 2; mt2++) {
                        int mt = 2 * m1 + mt2;
                        uint4 a = XP[(mt * 16 + ks) * 32 + lane];
                        mma16(a1[mt2][0], a, bc0.x, bc0.y);
                        mma16(a1[mt2][1], a, bc1.x, bc1.y);
                    }
                }
            }
            // bias + exact GELU -> H[sc&3]. Safe without barrier: stage t-1's
            // GEMM2 read buffers {2t+2, 2t+3} mod 4, disjoint from {2t, 2t+1}.
            uint32_t* HB = &smu[HP_U + (sc & 3) * 2048];
            int ks2 = 2 * ch + n1;
#pragma unroll
            for (int mt2 = 0; mt2 < 2; mt2++) {
                int mt = 2 * m1 + mt2;
                int rowbase = ((mt * 4 + ks2) * 32 + gg * 4 + cc) * 4;
#pragma unroll
                for (int tt = 0; tt < 2; tt++) {
                    int nt = 2 * n1 + tt;
                    int c0 = jc * 32 + nt * 8 + 2 * cc;
                    float bx = sm[B1_F + c0];
                    float by = sm[B1_F + c0 + 1];
                    float4 v = a1[mt2][tt];
                    uint2 hv;
                    hv.x = pk(gelu_exact(v.x + bx), gelu_exact(v.y + by));
                    hv.y = pk(gelu_exact(v.z + bx), gelu_exact(v.w + by));
                    *(uint2*)&HB[rowbase + 2 * tt] = hv;
                }
            }
        }

        // hoist W2 fragments for superchunk 2t (hides L2 latency over barrier)
        const uint2* W2s0 = W2B + (2 * t) * 4096;
        uint2 wb[2][4];
#pragma unroll
        for (int nt = 0; nt < 4; nt++) {
            wb[0][nt] = W2s0[(nb + nt) * 32 + lane];
            wb[1][nt] = W2s0[(32 + nb + nt) * 32 + lane];
        }
        __syncthreads();   // single barrier per stage: H[2t&3], H[(2t+1)&3] ready

        // ===== two superchunks of GEMM2 (sc ascending: bitwise-same acc) ====
        gemm2_step(acc, (const uint4*)&smu[HP_U + ((2 * t) & 3) * 2048],
                   W2s0, wb, nb, lane, true);
        gemm2_step(acc, (const uint4*)&smu[HP_U + ((2 * t + 1) & 3) * 2048],
                   W2B + (2 * t + 1) * 4096, wb, nb, lane, false);
    }

    // ---- epilogue: out[tok,:] += gate * (acc + b2), vector red ----
#pragma unroll
    for (int nt = 0; nt < 4; nt++) {
        int col = (nb + nt) * 8 + 2 * cc;
        float b2a = sm[B2_F + col], b2b = sm[B2_F + col + 1];
#pragma unroll
        for (int mt = 0; mt < 4; mt++) {
            float4 f = acc[mt][nt];
            int ra = mt * 16 + gg;
            int rb = ra + 8;
            if (ra < rows) {
                float gt = s_gate[ra];
                red2(out + (size_t)s_tok[ra] * DM + col,
                     gt * (f.x + b2a), gt * (f.y + b2b));
            }
            if (rb < rows) {
                float gt = s_gate[rb];
                red2(out + (size_t)s_tok[rb] * DM + col,
                     gt * (f.z + b2a), gt * (f.w + b2b));
            }
        }
    }
}

// ---------------- launch ----------------
extern "C" void kernel_launch(void* const* d_in, const int* in_sizes, int n_in,
                              void* d_out, int out_size) {
    const float* v0   = (const float*)d_in[0];
    const float* v1   = (const float*)d_in[1];
    const float* v2   = (const float*)d_in[2];
    const float* rw   = (const float*)d_in[3];
    const float* keys = (const float*)d_in[4];
    const float* W1   = (const float*)d_in[5];
    const float* b1   = (const float*)d_in[6];
    const float* W2   = (const float*)d_in[7];
    const float* b2   = (const float*)d_in[8];
    float* out = (float*)d_out;

    static void* cnt_addr = nullptr;
    if (!cnt_addr) cudaGetSymbolAddress(&cnt_addr, g_cnt);

    cudaFuncSetAttribute(ffn_kernel, cudaFuncAttributeMaxDynamicSharedMemorySize,
                         SMEM_BYTES);

    cudaMemsetAsync(cnt_addr, 0, sizeof(int) * NVIEW * NE, 0);

    prep_router_kernel<<<4608, 256, 0, 0>>>(W1, W2, v0, v1, v2, rw, keys, out);

    dim3 fgrid(N_TOK / TM, NE, NVIEW);   // 128 x 16 x 3, most blocks exit early
    ffn_kernel<<<fgrid, 256, SMEM_BYTES, 0>>>(v0, v1, v2, b1, b2, out);
}